// round 17
// baseline (speedup 1.0000x reference)
#include <cuda_runtime.h>
#include <cstdint>

// Problem constants: B=2, H=16, S=2048, D=64
#define SQ   2048
#define DD   64
#define NBH  32      // B*H
#define HPB  16      // heads per batch

// Row stats scratch (softmax max / sum per (bh, q) row).
__device__ float g_rowmax[NBH * SQ];
__device__ float g_rowsum[NBH * SQ];

typedef unsigned long long ull;

// ---------------- packed f32x2 helpers (2x fp32 FMA throughput) ---------------
__device__ __forceinline__ ull pk2(float lo, float hi) {
    ull r;
    asm("mov.b64 %0, {%1, %2};" : "=l"(r) : "f"(lo), "f"(hi));
    return r;
}
__device__ __forceinline__ void fma2(ull& d, ull a, ull b) {
    asm("fma.rn.f32x2 %0, %1, %2, %0;" : "+l"(d) : "l"(a), "l"(b));
}
__device__ __forceinline__ float2 up2(ull v) {
    float2 f;
    asm("mov.b64 {%0, %1}, %2;" : "=f"(f.x), "=f"(f.y) : "l"(v));
    return f;
}

// =============================================================================
// Kernel 1: scores = (Q @ K^T) * 0.125, masked.  Writes into prob region.
// 128x128 tile / block, 256 threads, 8x8 micro-tile per thread.
// Micro-tile columns/rows SPLIT as {t*4, 64+t*4} so every LDS.128 phase is
// bank-conflict-free.  D=64 in two 32-deep smem stages.
// grid: (ktile=16, qtile=16, bh=32)
// =============================================================================
__global__ __launch_bounds__(256) void qk_kernel(
    const float* __restrict__ Q, const float* __restrict__ K,
    const int* __restrict__ mask, float* __restrict__ Sc)
{
    __shared__ float Qs[32][132];   // [k][q]  transposed
    __shared__ float Ks[32][132];   // [k][kcol]

    const int bh = blockIdx.z;
    const int b  = bh / HPB;
    const int q0 = blockIdx.y * 128;
    const int k0 = blockIdx.x * 128;
    const int tx = threadIdx.x, ty = threadIdx.y;
    const int tid = ty * 16 + tx;

    const float* Qb = Q + (size_t)bh * SQ * DD;
    const float* Kb = K + (size_t)bh * SQ * DD;

    ull acc[8][4];
#pragma unroll
    for (int i = 0; i < 8; i++)
#pragma unroll
        for (int j = 0; j < 4; j++) acc[i][j] = 0ull;

    // Loader role: threads 0..127 transpose one Q row each; 128..255 one K row.
    const int lrow = tid & 127;
    const float* lsrc_base = (tid < 128)
        ? (Qb + (size_t)(q0 + lrow) * DD)
        : (Kb + (size_t)(k0 + lrow) * DD);
    float (*ldst)[132] = (tid < 128) ? Qs : Ks;

    for (int dh = 0; dh < 2; dh++) {
        if (dh) __syncthreads();
        {
            const float* src = lsrc_base + dh * 32;
#pragma unroll
            for (int v = 0; v < 8; v++) {
                float4 f = *(const float4*)(src + v * 4);
                ldst[v * 4 + 0][lrow] = f.x;
                ldst[v * 4 + 1][lrow] = f.y;
                ldst[v * 4 + 2][lrow] = f.z;
                ldst[v * 4 + 3][lrow] = f.w;
            }
        }
        __syncthreads();

#pragma unroll 8
        for (int kk = 0; kk < 32; kk++) {
            const float4 a0 = *(const float4*)(&Qs[kk][ty * 4]);
            const float4 a1 = *(const float4*)(&Qs[kk][64 + ty * 4]);
            const ulonglong2 b0 = *(const ulonglong2*)(&Ks[kk][tx * 4]);
            const ulonglong2 b1 = *(const ulonglong2*)(&Ks[kk][64 + tx * 4]);
            const float av[8] = {a0.x, a0.y, a0.z, a0.w, a1.x, a1.y, a1.z, a1.w};
#pragma unroll
            for (int i = 0; i < 8; i++) {
                const ull ap = pk2(av[i], av[i]);
                fma2(acc[i][0], ap, b0.x);
                fma2(acc[i][1], ap, b0.y);
                fma2(acc[i][2], ap, b1.x);
                fma2(acc[i][3], ap, b1.y);
            }
        }
    }

    // scale + mask + store  (rows: ty*4+i and 64+ty*4+i; cols: tx*4 and 64+tx*4)
    const int* mb = mask + (size_t)b * SQ * SQ;
    float* Sb = Sc + (size_t)bh * SQ * SQ;
    const int kc0 = k0 + tx * 4;
    const int kc1 = k0 + 64 + tx * 4;
#pragma unroll
    for (int i = 0; i < 8; i++) {
        const int q = q0 + ((i < 4) ? (ty * 4 + i) : (64 + ty * 4 + i - 4));
        const float2 c0 = up2(acc[i][0]);
        const float2 c1 = up2(acc[i][1]);
        const float2 c2 = up2(acc[i][2]);
        const float2 c3 = up2(acc[i][3]);
        float4 r0, r1;
        r0.x = c0.x * 0.125f; r0.y = c0.y * 0.125f;
        r0.z = c1.x * 0.125f; r0.w = c1.y * 0.125f;
        r1.x = c2.x * 0.125f; r1.y = c2.y * 0.125f;
        r1.z = c3.x * 0.125f; r1.w = c3.y * 0.125f;
        const int4 m0 = *(const int4*)(mb + (size_t)q * SQ + kc0);
        const int4 m1 = *(const int4*)(mb + (size_t)q * SQ + kc1);
        if (m0.x == 0) r0.x = -1e9f;
        if (m0.y == 0) r0.y = -1e9f;
        if (m0.z == 0) r0.z = -1e9f;
        if (m0.w == 0) r0.w = -1e9f;
        if (m1.x == 0) r1.x = -1e9f;
        if (m1.y == 0) r1.y = -1e9f;
        if (m1.z == 0) r1.z = -1e9f;
        if (m1.w == 0) r1.w = -1e9f;
        *(float4*)(Sb + (size_t)q * SQ + kc0) = r0;
        *(float4*)(Sb + (size_t)q * SQ + kc1) = r1;
    }
}

// =============================================================================
// Kernel 2: per-row max and sum(exp(x - max)).  One block (256 thr) per row.
// =============================================================================
__global__ __launch_bounds__(256) void rowstats_kernel(const float* __restrict__ Sc)
{
    const int row = blockIdx.x;
    const int tid = threadIdx.x;
    const float4* p = (const float4*)(Sc + (size_t)row * SQ);

    const float4 v0 = p[tid];
    const float4 v1 = p[tid + 256];

    float m = fmaxf(fmaxf(fmaxf(v0.x, v0.y), fmaxf(v0.z, v0.w)),
                    fmaxf(fmaxf(v1.x, v1.y), fmaxf(v1.z, v1.w)));
#pragma unroll
    for (int o = 16; o > 0; o >>= 1)
        m = fmaxf(m, __shfl_xor_sync(0xffffffffu, m, o));

    __shared__ float sm[8];
    __shared__ float ss[8];
    if ((tid & 31) == 0) sm[tid >> 5] = m;
    __syncthreads();
    m = sm[0];
#pragma unroll
    for (int i = 1; i < 8; i++) m = fmaxf(m, sm[i]);

    float s = __expf(v0.x - m) + __expf(v0.y - m) + __expf(v0.z - m) + __expf(v0.w - m)
            + __expf(v1.x - m) + __expf(v1.y - m) + __expf(v1.z - m) + __expf(v1.w - m);
#pragma unroll
    for (int o = 16; o > 0; o >>= 1)
        s += __shfl_xor_sync(0xffffffffu, s, o);
    if ((tid & 31) == 0) ss[tid >> 5] = s;
    __syncthreads();
    if (tid == 0) {
        float t = ss[0];
#pragma unroll
        for (int i = 1; i < 8; i++) t += ss[i];
        g_rowmax[row] = m;
        g_rowsum[row] = t;
    }
}

// =============================================================================
// Kernel 3: p = exp(s-m)/l written back in place (final attn_prob)
// AND context = P @ V.  256 queries x D=64 per block, 16x4 micro-tile
// (rows in 4 groups of 64).  K processed in 64 tiles of 32.
// Staging is row-per-thread: conflict-free transpose STS, one (m,1/l) per thread.
// grid: (qtile=8, bh=32)
// =============================================================================
__global__ __launch_bounds__(256) void pv_kernel(
    const float* __restrict__ V, float* __restrict__ P,
    float* __restrict__ ctx)
{
    __shared__ float Ps[32][260];   // [k][q]  transposed probs (260*4B: 16B mult)
    __shared__ float Vs[32][64];    // [k][d]  natural

    const int bh = blockIdx.y;
    const int q0 = blockIdx.x * 256;
    const int tx = threadIdx.x, ty = threadIdx.y;
    const int tid = ty * 16 + tx;

    float* Pb = P + (size_t)bh * SQ * SQ;
    const float* Vb = V + (size_t)bh * SQ * DD;

    // Staging role: this thread owns row (q0 + tid) entirely.
    const float sm  = g_rowmax[(size_t)bh * SQ + q0 + tid];
    const float srl = 1.0f / g_rowsum[(size_t)bh * SQ + q0 + tid];
    float* prow_base = Pb + (size_t)(q0 + tid) * SQ;

    ull acc[16][2];
#pragma unroll
    for (int i = 0; i < 16; i++) { acc[i][0] = 0ull; acc[i][1] = 0ull; }

    for (int kt = 0; kt < 64; kt++) {
        const int k0 = kt * 32;
        if (kt) __syncthreads();

        // Stage P: row tid, 32 cols: softmax transform, write final prob to
        // gmem, store transposed (STS conflict-free: bank = 4c + tid).
        {
            float4* prow = (float4*)(prow_base + k0);
#pragma unroll
            for (int v = 0; v < 8; v++) {
                float4 s4 = prow[v];
                float4 p4;
                p4.x = __expf(s4.x - sm) * srl;
                p4.y = __expf(s4.y - sm) * srl;
                p4.z = __expf(s4.z - sm) * srl;
                p4.w = __expf(s4.w - sm) * srl;
                prow[v] = p4;                    // final attn_prob
                const int c = v * 4;
                Ps[c + 0][tid] = p4.x;
                Ps[c + 1][tid] = p4.y;
                Ps[c + 2][tid] = p4.z;
                Ps[c + 3][tid] = p4.w;
            }
        }
        // Stage V tile: 32x64 floats contiguous -> flat copy.
        {
            const float4* vsrc = (const float4*)(Vb + (size_t)k0 * DD);
            float4* vdst = (float4*)(&Vs[0][0]);
            vdst[tid]       = vsrc[tid];
            vdst[tid + 256] = vsrc[tid + 256];
        }
        __syncthreads();

#pragma unroll 8
        for (int kk = 0; kk < 32; kk++) {
            const ulonglong2 bb = *(const ulonglong2*)(&Vs[kk][tx * 4]);
#pragma unroll
            for (int g = 0; g < 4; g++) {
                const float4 a = *(const float4*)(&Ps[kk][g * 64 + ty * 4]);
                const int r = g * 4;
                ull ap;
                ap = pk2(a.x, a.x); fma2(acc[r+0][0], ap, bb.x); fma2(acc[r+0][1], ap, bb.y);
                ap = pk2(a.y, a.y); fma2(acc[r+1][0], ap, bb.x); fma2(acc[r+1][1], ap, bb.y);
                ap = pk2(a.z, a.z); fma2(acc[r+2][0], ap, bb.x); fma2(acc[r+2][1], ap, bb.y);
                ap = pk2(a.w, a.w); fma2(acc[r+3][0], ap, bb.x); fma2(acc[r+3][1], ap, bb.y);
            }
        }
    }

    float* cb = ctx + (size_t)bh * SQ * DD;
#pragma unroll
    for (int g = 0; g < 4; g++)
#pragma unroll
        for (int i = 0; i < 4; i++) {
            const float2 c0 = up2(acc[g * 4 + i][0]);
            const float2 c1 = up2(acc[g * 4 + i][1]);
            float4 r;
            r.x = c0.x; r.y = c0.y; r.z = c1.x; r.w = c1.y;
            const int q = q0 + g * 64 + ty * 4 + i;
            *(float4*)(cb + (size_t)q * DD + tx * 4) = r;
        }
}

// =============================================================================
// kernel_launch: inputs Q, K, V, attn_mask.
// d_out: [context (B*H*S*D) | attn_prob (B*H*S*S)], float32.
// =============================================================================
extern "C" void kernel_launch(void* const* d_in, const int* in_sizes, int n_in,
                              void* d_out, int out_size)
{
    const float* Q   = (const float*)d_in[0];
    const float* K   = (const float*)d_in[1];
    const float* V   = (const float*)d_in[2];
    const int*   msk = (const int*)d_in[3];

    float* ctx  = (float*)d_out;
    float* prob = (float*)d_out + (size_t)NBH * SQ * DD;

    dim3 blk(16, 16);

    // 1) scores into prob region
    dim3 g1(SQ / 128, SQ / 128, NBH);                // (16, 16, 32)
    qk_kernel<<<g1, blk>>>(Q, K, msk, prob);

    // 2) per-row max / sumexp
    rowstats_kernel<<<NBH * SQ, 256>>>(prob);

    // 3) normalize in place + context GEMM
    dim3 g3(SQ / 256, NBH);                          // (8, 32)
    pv_kernel<<<g3, blk>>>(V, prob, ctx);
}